// round 2
// baseline (speedup 1.0000x reference)
#include <cuda_runtime.h>

#define BATCH 16384
#define NEG 5
#define WARPS_PER_BLOCK 16
#define THREADS (WARPS_PER_BLOCK * 32)          // 512
#define NBLOCKS (BATCH / WARPS_PER_BLOCK)       // 1024

__device__ float g_partials[NBLOCKS];
__device__ unsigned int g_count;                // zero-init; last block resets to 0

__device__ __forceinline__ float logsig(float x) {
    // stable log(sigmoid(x)) = min(x,0) - log1p(exp(-|x|))
    return fminf(x, 0.0f) - log1pf(expf(-fabsf(x)));
}

__global__ void __launch_bounds__(THREADS)
sg_fused(const float* __restrict__ emb,
         const int* __restrict__ centers,
         const int* __restrict__ contexts,
         const int* __restrict__ negs,
         float* __restrict__ out) {
    const int lane = threadIdx.x & 31;
    const int warp = threadIdx.x >> 5;
    const int b = blockIdx.x * WARPS_PER_BLOCK + warp;   // batch element

    // Row = 128 floats = 32 float4; lane i takes float4 i -> 512B coalesced per row.
    const float4* e4 = reinterpret_cast<const float4*>(emb);

    // Gather all indices first so the 7 row loads issue back-to-back (MLP=7/warp).
    const int ic = centers[b];
    const int it = contexts[b];
    const int in0 = negs[b * NEG + 0];
    const int in1 = negs[b * NEG + 1];
    const int in2 = negs[b * NEG + 2];
    const int in3 = negs[b * NEG + 3];
    const int in4 = negs[b * NEG + 4];

    const float4 u  = e4[(size_t)ic  * 32 + lane];
    const float4 v  = e4[(size_t)it  * 32 + lane];
    const float4 w0 = e4[(size_t)in0 * 32 + lane];
    const float4 w1 = e4[(size_t)in1 * 32 + lane];
    const float4 w2 = e4[(size_t)in2 * 32 + lane];
    const float4 w3 = e4[(size_t)in3 * 32 + lane];
    const float4 w4 = e4[(size_t)in4 * 32 + lane];

    // sum_k (u . nv_k) == u . (sum_k nv_k)
    float4 ns;
    ns.x = w0.x + w1.x + w2.x + w3.x + w4.x;
    ns.y = w0.y + w1.y + w2.y + w3.y + w4.y;
    ns.z = w0.z + w1.z + w2.z + w3.z + w4.z;
    ns.w = w0.w + w1.w + w2.w + w3.w + w4.w;

    float pos = u.x * v.x  + u.y * v.y  + u.z * v.z  + u.w * v.w;
    float neg = u.x * ns.x + u.y * ns.y + u.z * ns.z + u.w * ns.w;

    #pragma unroll
    for (int o = 16; o > 0; o >>= 1) {
        pos += __shfl_xor_sync(0xffffffffu, pos, o);
        neg += __shfl_xor_sync(0xffffffffu, neg, o);
    }

    __shared__ float sm[WARPS_PER_BLOCK];
    __shared__ bool is_last;
    if (lane == 0)
        sm[warp] = logsig(pos) + logsig(-neg);
    __syncthreads();

    // Thread 0: block partial -> gmem, then bump completion counter.
    if (threadIdx.x == 0) {
        float s = 0.0f;
        #pragma unroll
        for (int i = 0; i < WARPS_PER_BLOCK; i++) s += sm[i];
        g_partials[blockIdx.x] = s;
        __threadfence();
        unsigned int t = atomicAdd(&g_count, 1u);
        is_last = (t == NBLOCKS - 1);
    }
    __syncthreads();

    // Last block to finish performs the final (deterministic, fixed-order) reduction.
    if (is_last) {
        __shared__ float red[THREADS];
        float s = 0.0f;
        #pragma unroll
        for (int i = 0; i < NBLOCKS / THREADS; i++)         // 2 per thread
            s += g_partials[threadIdx.x + i * THREADS];
        red[threadIdx.x] = s;
        __syncthreads();
        #pragma unroll
        for (int o = THREADS / 2; o > 0; o >>= 1) {
            if (threadIdx.x < o) red[threadIdx.x] += red[threadIdx.x + o];
            __syncthreads();
        }
        if (threadIdx.x == 0) {
            out[0] = -red[0];
            g_count = 0;   // reset for next replay (keeps launch deterministic)
        }
    }
}

extern "C" void kernel_launch(void* const* d_in, const int* in_sizes, int n_in,
                              void* d_out, int out_size) {
    const float* emb      = (const float*)d_in[0];
    const int*   centers  = (const int*)  d_in[1];
    const int*   contexts = (const int*)  d_in[2];
    const int*   negs     = (const int*)  d_in[3];
    float*       out      = (float*)d_out;

    sg_fused<<<NBLOCKS, THREADS>>>(emb, centers, contexts, negs, out);
}

// round 3
// speedup vs baseline: 1.0225x; 1.0225x over previous
#include <cuda_runtime.h>

#define BATCH 16384
#define NEG 5
#define WARPS_PER_BLOCK 8
#define THREADS (WARPS_PER_BLOCK * 32)              // 256
#define ELEMS_PER_WARP 2
#define ELEMS_PER_BLOCK (WARPS_PER_BLOCK * ELEMS_PER_WARP)   // 16
#define NBLOCKS (BATCH / ELEMS_PER_BLOCK)           // 1024

__device__ float g_partials[NBLOCKS];
__device__ unsigned int g_count;                    // zero-init; last block resets

__device__ __forceinline__ float logsig(float x) {
    // stable log(sigmoid(x)) = min(x,0) - log1p(exp(-|x|))
    return fminf(x, 0.0f) - log1pf(expf(-fabsf(x)));
}

__global__ void __launch_bounds__(THREADS)
sg_fused(const float* __restrict__ emb,
         const int* __restrict__ centers,
         const int* __restrict__ contexts,
         const int* __restrict__ negs,
         float* __restrict__ out) {
    const int lane = threadIdx.x & 31;
    const int warp = threadIdx.x >> 5;
    const int b0 = blockIdx.x * ELEMS_PER_BLOCK + warp * ELEMS_PER_WARP;
    const int b1 = b0 + 1;

    const float4* e4 = reinterpret_cast<const float4*>(emb);

    // ---- issue ALL index loads first (14 independent LDGs) ----
    const int ic0 = centers[b0],  ic1 = centers[b1];
    const int it0 = contexts[b0], it1 = contexts[b1];
    const int n00 = negs[b0 * NEG + 0], n01 = negs[b0 * NEG + 1],
              n02 = negs[b0 * NEG + 2], n03 = negs[b0 * NEG + 3],
              n04 = negs[b0 * NEG + 4];
    const int n10 = negs[b1 * NEG + 0], n11 = negs[b1 * NEG + 1],
              n12 = negs[b1 * NEG + 2], n13 = negs[b1 * NEG + 3],
              n14 = negs[b1 * NEG + 4];

    // ---- issue ALL 14 row loads back-to-back (MLP=14/warp) ----
    // Row = 128 floats = 32 float4; lane i takes float4 i -> 512B coalesced.
    const float4 u0  = e4[(size_t)ic0 * 32 + lane];
    const float4 v0  = e4[(size_t)it0 * 32 + lane];
    const float4 a0  = e4[(size_t)n00 * 32 + lane];
    const float4 a1  = e4[(size_t)n01 * 32 + lane];
    const float4 a2  = e4[(size_t)n02 * 32 + lane];
    const float4 a3  = e4[(size_t)n03 * 32 + lane];
    const float4 a4  = e4[(size_t)n04 * 32 + lane];
    const float4 u1  = e4[(size_t)ic1 * 32 + lane];
    const float4 v1  = e4[(size_t)it1 * 32 + lane];
    const float4 c0  = e4[(size_t)n10 * 32 + lane];
    const float4 c1  = e4[(size_t)n11 * 32 + lane];
    const float4 c2  = e4[(size_t)n12 * 32 + lane];
    const float4 c3  = e4[(size_t)n13 * 32 + lane];
    const float4 c4  = e4[(size_t)n14 * 32 + lane];

    // sum_k (u . nv_k) == u . (sum_k nv_k)
    float4 s0, s1;
    s0.x = a0.x + a1.x + a2.x + a3.x + a4.x;
    s0.y = a0.y + a1.y + a2.y + a3.y + a4.y;
    s0.z = a0.z + a1.z + a2.z + a3.z + a4.z;
    s0.w = a0.w + a1.w + a2.w + a3.w + a4.w;
    s1.x = c0.x + c1.x + c2.x + c3.x + c4.x;
    s1.y = c0.y + c1.y + c2.y + c3.y + c4.y;
    s1.z = c0.z + c1.z + c2.z + c3.z + c4.z;
    s1.w = c0.w + c1.w + c2.w + c3.w + c4.w;

    float pos0 = u0.x * v0.x + u0.y * v0.y + u0.z * v0.z + u0.w * v0.w;
    float neg0 = u0.x * s0.x + u0.y * s0.y + u0.z * s0.z + u0.w * s0.w;
    float pos1 = u1.x * v1.x + u1.y * v1.y + u1.z * v1.z + u1.w * v1.w;
    float neg1 = u1.x * s1.x + u1.y * s1.y + u1.z * s1.z + u1.w * s1.w;

    #pragma unroll
    for (int o = 16; o > 0; o >>= 1) {
        pos0 += __shfl_xor_sync(0xffffffffu, pos0, o);
        neg0 += __shfl_xor_sync(0xffffffffu, neg0, o);
        pos1 += __shfl_xor_sync(0xffffffffu, pos1, o);
        neg1 += __shfl_xor_sync(0xffffffffu, neg1, o);
    }

    __shared__ float sm[WARPS_PER_BLOCK];
    __shared__ bool is_last;
    if (lane == 0)
        sm[warp] = (logsig(pos0) + logsig(-neg0)) +
                   (logsig(pos1) + logsig(-neg1));
    __syncthreads();

    if (threadIdx.x == 0) {
        float s = 0.0f;
        #pragma unroll
        for (int i = 0; i < WARPS_PER_BLOCK; i++) s += sm[i];
        g_partials[blockIdx.x] = s;
        __threadfence();
        unsigned int t = atomicAdd(&g_count, 1u);
        is_last = (t == NBLOCKS - 1);
    }
    __syncthreads();

    // Last block: deterministic fixed-order final reduction of 1024 partials.
    if (is_last) {
        __shared__ float red[THREADS];
        float s = 0.0f;
        #pragma unroll
        for (int i = 0; i < NBLOCKS / THREADS; i++)   // 4 per thread
            s += g_partials[threadIdx.x + i * THREADS];
        red[threadIdx.x] = s;
        __syncthreads();
        #pragma unroll
        for (int o = THREADS / 2; o > 0; o >>= 1) {
            if (threadIdx.x < o) red[threadIdx.x] += red[threadIdx.x + o];
            __syncthreads();
        }
        if (threadIdx.x == 0) {
            out[0] = -red[0];
            g_count = 0;   // reset for next graph replay (determinism)
        }
    }
}

extern "C" void kernel_launch(void* const* d_in, const int* in_sizes, int n_in,
                              void* d_out, int out_size) {
    const float* emb      = (const float*)d_in[0];
    const int*   centers  = (const int*)  d_in[1];
    const int*   contexts = (const int*)  d_in[2];
    const int*   negs     = (const int*)  d_in[3];
    float*       out      = (float*)d_out;

    sg_fused<<<NBLOCKS, THREADS>>>(emb, centers, contexts, negs, out);
}